// round 7
// baseline (speedup 1.0000x reference)
#include <cuda_runtime.h>
#include <cuda_fp16.h>
#include <cstdint>

// ============================================================================
// Problem constants
// ============================================================================
#define IN_DIM   4096
#define OUT_DIM  4096
#define MROWS    8192        // BSZ * SEQ
#define TRANK    64
#define LORA_SCALE 2.0f      // alpha/r = 32/16 for every adapter

// GEMM tiling: canonical big-tile config.
// CTA 128x256, 256 threads, 8 warps (2m x 4n), warp tile 64x64.
// 6-stage cp.async pipeline, 1 CTA/SM, high registers (~190).
#define BM 128
#define BN 256
#define BK 32
#define KT (IN_DIM / BK)          // 128 k-tiles
#define STAGES 6
#define A_BYTES (BM * BK * 2)     // 8192
#define B_BYTES (BN * BK * 2)     // 16384
#define STAGE_BYTES (A_BYTES + B_BYTES)   // 24576
#define SMEM_TOTAL (STAGES * STAGE_BYTES) // 147456

// grid rasterization: group 8 m-tiles per n-panel for L2/DRAM reuse
#define NUM_PID_M (MROWS / BM)    // 64
#define NUM_PID_N (OUT_DIM / BN)  // 16
#define GRPM 8

// ============================================================================
// Device scratch (allocation-free rule: __device__ globals)
// ============================================================================
__device__ __half d_Xh[(size_t)MROWS * IN_DIM];    // 64 MiB
__device__ __half d_Wh[(size_t)OUT_DIM * IN_DIM];  // 32 MiB

// ============================================================================
// PTX helpers
// ============================================================================
__device__ __forceinline__ uint32_t smem_u32(const void* p) {
    uint32_t a;
    asm("{ .reg .u64 t; cvta.to.shared.u64 t, %1; cvt.u32.u64 %0, t; }"
        : "=r"(a) : "l"(p));
    return a;
}

#define CP_ASYNC16(dst, src) \
    asm volatile("cp.async.cg.shared.global [%0], [%1], 16;" \
                 :: "r"(dst), "l"(src) : "memory")
#define CP_COMMIT() asm volatile("cp.async.commit_group;" ::: "memory")
#define CP_WAIT4()  asm volatile("cp.async.wait_group 4;" ::: "memory")

__device__ __forceinline__ void ldmatrix_x4(uint32_t& r0, uint32_t& r1,
                                            uint32_t& r2, uint32_t& r3,
                                            uint32_t addr) {
    asm volatile("ldmatrix.sync.aligned.m8n8.x4.shared.b16 {%0,%1,%2,%3}, [%4];"
                 : "=r"(r0), "=r"(r1), "=r"(r2), "=r"(r3) : "r"(addr));
}
__device__ __forceinline__ void mma16816(float* c, const uint32_t* a,
                                         const uint32_t* b) {
    asm volatile(
        "mma.sync.aligned.m16n8k16.row.col.f32.f16.f16.f32 "
        "{%0,%1,%2,%3}, {%4,%5,%6,%7}, {%8,%9}, {%0,%1,%2,%3};"
        : "+f"(c[0]), "+f"(c[1]), "+f"(c[2]), "+f"(c[3])
        : "r"(a[0]), "r"(a[1]), "r"(a[2]), "r"(a[3]), "r"(b[0]), "r"(b[1]));
}

// Swizzle for 64-byte rows, 16B chunks: phys_chunk = chunk ^ ((row>>1)&3)
__device__ __forceinline__ uint32_t sw_off(int row, int chunk) {
    return (uint32_t)(row * 64 + ((chunk ^ ((row >> 1) & 3)) << 4));
}

// ============================================================================
// Prologue 1: x (fp32) -> d_Xh (fp16, RN)
// ============================================================================
__global__ void cvt_x_kernel(const float4* __restrict__ x) {
    const int n8 = (MROWS * IN_DIM) / 8;
    for (int i = blockIdx.x * blockDim.x + threadIdx.x; i < n8;
         i += gridDim.x * blockDim.x) {
        float4 a = x[2 * i];
        float4 b = x[2 * i + 1];
        __half2 h0 = __floats2half2_rn(a.x, a.y);
        __half2 h1 = __floats2half2_rn(a.z, a.w);
        __half2 h2 = __floats2half2_rn(b.x, b.y);
        __half2 h3 = __floats2half2_rn(b.z, b.w);
        uint4 v;
        v.x = *reinterpret_cast<uint32_t*>(&h0);
        v.y = *reinterpret_cast<uint32_t*>(&h1);
        v.z = *reinterpret_cast<uint32_t*>(&h2);
        v.w = *reinterpret_cast<uint32_t*>(&h3);
        reinterpret_cast<uint4*>(d_Xh)[i] = v;
    }
}

// ============================================================================
// Prologue 2: W_eff = W + 2 * B @ A  -> d_Wh (fp16)
// ============================================================================
__global__ void build_weff_kernel(const float* __restrict__ W,
                                  const float* __restrict__ A,   // [64, 4096]
                                  const float* __restrict__ B) { // [4096, 64]
    __shared__ float sA[64][65];
    __shared__ float sB[64][65];
    const int tid = threadIdx.x;
    const int n0 = blockIdx.y * 64;
    const int k0 = blockIdx.x * 64;

    for (int t = tid; t < 64 * 64; t += 256) {
        int i = t >> 6, c = t & 63;
        sA[i][c] = A[i * IN_DIM + k0 + c];
        sB[i][c] = LORA_SCALE * B[(size_t)(n0 + i) * TRANK + c];
    }
    __syncthreads();

    const int tj = tid & 15, ti = tid >> 4;
    float acc[4][4] = {};
#pragma unroll 8
    for (int r = 0; r < 64; r++) {
        float bv[4], av[4];
#pragma unroll
        for (int q = 0; q < 4; q++) { bv[q] = sB[ti * 4 + q][r]; av[q] = sA[r][tj * 4 + q]; }
#pragma unroll
        for (int p = 0; p < 4; p++)
#pragma unroll
            for (int q = 0; q < 4; q++) acc[p][q] += bv[p] * av[q];
    }
#pragma unroll
    for (int p = 0; p < 4; p++) {
        int n = n0 + ti * 4 + p;
#pragma unroll
        for (int q = 0; q < 4; q++) {
            int k = k0 + tj * 4 + q;
            d_Wh[(size_t)n * IN_DIM + k] =
                __float2half_rn(W[(size_t)n * IN_DIM + k] + acc[p][q]);
        }
    }
}

// ============================================================================
// Main GEMM: out[8192,4096] = Xh @ Whᵀ  (fp16 in, fp32 accum, mma.sync)
// CTA 128x256, 8 warps (2m x 4n), warp tile 64x64, 6-stage pipeline,
// per-k-tile wait_group(4) + __syncthreads.
// ============================================================================
__global__ void __launch_bounds__(256, 1) lora_gemm_kernel(float* __restrict__ out) {
    extern __shared__ __align__(1024) char smem[];
    const uint32_t sb = smem_u32(smem);
    const int tid = threadIdx.x;
    const int wid = tid >> 5, lane = tid & 31;
    const int warp_m = wid & 1;          // 0..1  (64 rows each)
    const int warp_n = wid >> 1;         // 0..3  (64 cols each)

    // ---- grouped rasterization ----
    const int pid = blockIdx.x;
    const int group_size = GRPM * NUM_PID_N;
    const int group_id = pid / group_size;
    const int pid_in = pid - group_id * group_size;
    const int pid_m = group_id * GRPM + (pid_in % GRPM);
    const int pid_n = pid_in / GRPM;

    const int mbase = pid_m * BM;
    const int nbase = pid_n * BN;

    const __half* gX = d_Xh;
    const __half* gW = d_Wh;

    // ---- cp.async loader: 256 threads, 16B chunks ----
    // A: 128 rows x 4 chunks = 512 (2/thread); B: 256 rows x 4 = 1024 (4/thread)
    const int ld_row = tid >> 2;          // 0..63
    const int ld_c   = tid & 3;           // 0..3

    auto issue_stage = [&](int kt, int s) {
        const uint32_t base = sb + s * STAGE_BYTES;
        const size_t gk = (size_t)kt * BK + ld_c * 8;
#pragma unroll
        for (int p = 0; p < 2; p++) {
            const int row = ld_row + p * 64;
            CP_ASYNC16(base + sw_off(row, ld_c),
                       gX + (size_t)(mbase + row) * IN_DIM + gk);
        }
#pragma unroll
        for (int p = 0; p < 4; p++) {
            const int row = ld_row + p * 64;
            CP_ASYNC16(base + A_BYTES + sw_off(row, ld_c),
                       gW + (size_t)(nbase + row) * IN_DIM + gk);
        }
    };

    // ---- prologue: fill 5 stages ----
#pragma unroll
    for (int i = 0; i < STAGES - 1; i++) {
        issue_stage(i, i);
        CP_COMMIT();
    }

    // ---- ldmatrix lane addressing ----
    // A: x4 over rows (lane&15), chunk halves by lane>>4
    const int a_row_l = warp_m * 64 + (lane & 15);
    const int a_cgrp  = lane >> 4;          // 0..1
    // B paired x4 (two n8-tiles per instr):
    //   row   = warp_n*64 + np*16 + (lane&7) + ((lane>>4)&1)*8
    //   chunk = ks*2 + ((lane>>3)&1)
    const int b_row_l = warp_n * 64 + (lane & 7) + (((lane >> 4) & 1) << 3);
    const int b_cgrp  = (lane >> 3) & 1;

    float acc[4][8][4] = {};   // [mt][nt][frag] = 128 regs

    int s = 0;
    for (int kt = 0; kt < KT; kt++) {
        CP_WAIT4();          // stage kt's group retired (own view)
        __syncthreads();     // all 8 warps done with stage kt-1's slot

        // prefetch stage kt+5 into the slot read at iteration kt-1
        const int ktn = kt + STAGES - 1;
        if (ktn < KT) {
            int sn = s + STAGES - 1;
            if (sn >= STAGES) sn -= STAGES;
            issue_stage(ktn, sn);
        }
        CP_COMMIT();

        const uint32_t abase = sb + s * STAGE_BYTES;
        const uint32_t bbase = abase + A_BYTES;

#pragma unroll
        for (int ks = 0; ks < 2; ks++) {
            uint32_t af[4][4];
            uint32_t bf[8][2];
#pragma unroll
            for (int mt = 0; mt < 4; mt++) {
                const int row = a_row_l + mt * 16;
                ldmatrix_x4(af[mt][0], af[mt][1], af[mt][2], af[mt][3],
                            abase + sw_off(row, ks * 2 + a_cgrp));
            }
#pragma unroll
            for (int np = 0; np < 4; np++) {   // two n8-tiles per ldmatrix
                const int row = b_row_l + np * 16;
                ldmatrix_x4(bf[2 * np][0], bf[2 * np][1],
                            bf[2 * np + 1][0], bf[2 * np + 1][1],
                            bbase + sw_off(row, ks * 2 + b_cgrp));
            }
#pragma unroll
            for (int mt = 0; mt < 4; mt++)
#pragma unroll
                for (int nt = 0; nt < 8; nt++)
                    mma16816(acc[mt][nt], af[mt], bf[nt]);
        }

        if (++s == STAGES) s = 0;
    }

    // ---- epilogue: registers -> gmem ----
    const int er = lane >> 2;            // 0..7
    const int ec = (lane & 3) * 2;       // 0,2,4,6
#pragma unroll
    for (int mt = 0; mt < 4; mt++) {
#pragma unroll
        for (int nt = 0; nt < 8; nt++) {
            const int r0 = mbase + warp_m * 64 + mt * 16 + er;
            const int c0 = nbase + warp_n * 64 + nt * 8 + ec;
            float2 v0 = make_float2(acc[mt][nt][0], acc[mt][nt][1]);
            float2 v1 = make_float2(acc[mt][nt][2], acc[mt][nt][3]);
            *reinterpret_cast<float2*>(out + (size_t)r0 * OUT_DIM + c0) = v0;
            *reinterpret_cast<float2*>(out + (size_t)(r0 + 8) * OUT_DIM + c0) = v1;
        }
    }
}

// ============================================================================
// Host side
// ============================================================================
extern "C" void kernel_launch(void* const* d_in, const int* in_sizes, int n_in,
                              void* d_out, int out_size) {
    (void)in_sizes; (void)n_in; (void)out_size;
    const float* x  = (const float*)d_in[0];
    const float* w  = (const float*)d_in[1];
    const float* la = (const float*)d_in[2];
    const float* lb = (const float*)d_in[3];
    float* out = (float*)d_out;

    cvt_x_kernel<<<4096, 256>>>(reinterpret_cast<const float4*>(x));
    build_weff_kernel<<<dim3(IN_DIM / 64, OUT_DIM / 64), 256>>>(w, la, lb);

    cudaFuncSetAttribute(lora_gemm_kernel,
                         cudaFuncAttributeMaxDynamicSharedMemorySize, SMEM_TOTAL);
    lora_gemm_kernel<<<NUM_PID_M * NUM_PID_N, 256, SMEM_TOTAL>>>(out);
}

// round 9
// speedup vs baseline: 1.3382x; 1.3382x over previous
#include <cuda_runtime.h>
#include <cuda_fp16.h>
#include <cstdint>

// ============================================================================
// Problem constants
// ============================================================================
#define IN_DIM   4096
#define OUT_DIM  4096
#define MROWS    8192        // BSZ * SEQ
#define TRANK    64
#define LORA_SCALE 2.0f      // alpha/r = 32/16 for every adapter

// GEMM tiling: CTA 128x128 with FOUR warps (128 thr), warp tile 64x64.
// 2 CTAs/SM preserved (128thr*~180regs*2 fits RF; 96KB smem*2 = 192KB).
// smem traffic per CTA-ktile: 16KB fill + 32KB LDSM (amp 2+2) = 48KB.
#define BM 128
#define BN 128
#define BK 32
#define KT (IN_DIM / BK)          // 128 k-tiles
#define STAGES 6
#define A_BYTES (BM * BK * 2)     // 8192
#define B_BYTES (BN * BK * 2)     // 8192
#define STAGE_BYTES (A_BYTES + B_BYTES)   // 16384
#define SMEM_TOTAL (STAGES * STAGE_BYTES) // 98304 (x2 CTAs = 192KB <= 228KB)

// grid rasterization: group 8 m-tiles per n-panel for L2/DRAM reuse
#define NUM_PID_M (MROWS / BM)    // 64
#define NUM_PID_N (OUT_DIM / BN)  // 32
#define GRPM 8

// ============================================================================
// Device scratch (allocation-free rule: __device__ globals)
// ============================================================================
__device__ __half d_Xh[(size_t)MROWS * IN_DIM];    // 64 MiB
__device__ __half d_Wh[(size_t)OUT_DIM * IN_DIM];  // 32 MiB

// ============================================================================
// PTX helpers
// ============================================================================
__device__ __forceinline__ uint32_t smem_u32(const void* p) {
    uint32_t a;
    asm("{ .reg .u64 t; cvta.to.shared.u64 t, %1; cvt.u32.u64 %0, t; }"
        : "=r"(a) : "l"(p));
    return a;
}

#define CP_ASYNC16(dst, src) \
    asm volatile("cp.async.cg.shared.global [%0], [%1], 16;" \
                 :: "r"(dst), "l"(src) : "memory")
#define CP_COMMIT() asm volatile("cp.async.commit_group;" ::: "memory")
#define CP_WAIT4()  asm volatile("cp.async.wait_group 4;" ::: "memory")

__device__ __forceinline__ void ldmatrix_x4(uint32_t& r0, uint32_t& r1,
                                            uint32_t& r2, uint32_t& r3,
                                            uint32_t addr) {
    asm volatile("ldmatrix.sync.aligned.m8n8.x4.shared.b16 {%0,%1,%2,%3}, [%4];"
                 : "=r"(r0), "=r"(r1), "=r"(r2), "=r"(r3) : "r"(addr));
}
__device__ __forceinline__ void mma16816(float* c, const uint32_t* a,
                                         const uint32_t* b) {
    asm volatile(
        "mma.sync.aligned.m16n8k16.row.col.f32.f16.f16.f32 "
        "{%0,%1,%2,%3}, {%4,%5,%6,%7}, {%8,%9}, {%0,%1,%2,%3};"
        : "+f"(c[0]), "+f"(c[1]), "+f"(c[2]), "+f"(c[3])
        : "r"(a[0]), "r"(a[1]), "r"(a[2]), "r"(a[3]), "r"(b[0]), "r"(b[1]));
}

// Swizzle for 64-byte rows, 16B chunks: phys_chunk = chunk ^ ((row>>1)&3)
__device__ __forceinline__ uint32_t sw_off(int row, int chunk) {
    return (uint32_t)(row * 64 + ((chunk ^ ((row >> 1) & 3)) << 4));
}

// ============================================================================
// Prologue 1: x (fp32) -> d_Xh (fp16, RN)
// ============================================================================
__global__ void cvt_x_kernel(const float4* __restrict__ x) {
    const int n8 = (MROWS * IN_DIM) / 8;
    for (int i = blockIdx.x * blockDim.x + threadIdx.x; i < n8;
         i += gridDim.x * blockDim.x) {
        float4 a = x[2 * i];
        float4 b = x[2 * i + 1];
        __half2 h0 = __floats2half2_rn(a.x, a.y);
        __half2 h1 = __floats2half2_rn(a.z, a.w);
        __half2 h2 = __floats2half2_rn(b.x, b.y);
        __half2 h3 = __floats2half2_rn(b.z, b.w);
        uint4 v;
        v.x = *reinterpret_cast<uint32_t*>(&h0);
        v.y = *reinterpret_cast<uint32_t*>(&h1);
        v.z = *reinterpret_cast<uint32_t*>(&h2);
        v.w = *reinterpret_cast<uint32_t*>(&h3);
        reinterpret_cast<uint4*>(d_Xh)[i] = v;
    }
}

// ============================================================================
// Prologue 2: W_eff = W + 2 * B @ A  -> d_Wh (fp16)
// ============================================================================
__global__ void build_weff_kernel(const float* __restrict__ W,
                                  const float* __restrict__ A,   // [64, 4096]
                                  const float* __restrict__ B) { // [4096, 64]
    __shared__ float sA[64][65];
    __shared__ float sB[64][65];
    const int tid = threadIdx.x;
    const int n0 = blockIdx.y * 64;
    const int k0 = blockIdx.x * 64;

    for (int t = tid; t < 64 * 64; t += 256) {
        int i = t >> 6, c = t & 63;
        sA[i][c] = A[i * IN_DIM + k0 + c];
        sB[i][c] = LORA_SCALE * B[(size_t)(n0 + i) * TRANK + c];
    }
    __syncthreads();

    const int tj = tid & 15, ti = tid >> 4;
    float acc[4][4] = {};
#pragma unroll 8
    for (int r = 0; r < 64; r++) {
        float bv[4], av[4];
#pragma unroll
        for (int q = 0; q < 4; q++) { bv[q] = sB[ti * 4 + q][r]; av[q] = sA[r][tj * 4 + q]; }
#pragma unroll
        for (int p = 0; p < 4; p++)
#pragma unroll
            for (int q = 0; q < 4; q++) acc[p][q] += bv[p] * av[q];
    }
#pragma unroll
    for (int p = 0; p < 4; p++) {
        int n = n0 + ti * 4 + p;
#pragma unroll
        for (int q = 0; q < 4; q++) {
            int k = k0 + tj * 4 + q;
            d_Wh[(size_t)n * IN_DIM + k] =
                __float2half_rn(W[(size_t)n * IN_DIM + k] + acc[p][q]);
        }
    }
}

// ============================================================================
// Main GEMM: out[8192,4096] = Xh @ Whᵀ  (fp16 in, fp32 accum, mma.sync)
// CTA 128x128, 4 warps (2m x 2n), warp tile 64x64, 6-stage pipeline,
// per-k-tile wait_group(4) + __syncthreads. 2 CTAs/SM.
// ============================================================================
__global__ void __launch_bounds__(128, 2) lora_gemm_kernel(float* __restrict__ out) {
    extern __shared__ __align__(1024) char smem[];
    const uint32_t sb = smem_u32(smem);
    const int tid = threadIdx.x;
    const int wid = tid >> 5, lane = tid & 31;
    const int warp_m = wid & 1;          // 0..1  (64 rows each)
    const int warp_n = wid >> 1;         // 0..1  (64 cols each)

    // ---- grouped rasterization ----
    const int pid = blockIdx.x;
    const int group_size = GRPM * NUM_PID_N;
    const int group_id = pid / group_size;
    const int pid_in = pid - group_id * group_size;
    const int pid_m = group_id * GRPM + (pid_in % GRPM);
    const int pid_n = pid_in / GRPM;

    const int mbase = pid_m * BM;
    const int nbase = pid_n * BN;

    const __half* gX = d_Xh;
    const __half* gW = d_Wh;

    // ---- cp.async loader: 128 threads, 16B chunks, 4 row-passes each ----
    const int ld_row = tid >> 2;          // 0..31
    const int ld_c   = tid & 3;           // 0..3

    auto issue_stage = [&](int kt, int s) {
        const uint32_t base = sb + s * STAGE_BYTES;
        const size_t gk = (size_t)kt * BK + ld_c * 8;
#pragma unroll
        for (int p = 0; p < 4; p++) {
            const int row = ld_row + p * 32;
            const uint32_t off = sw_off(row, ld_c);
            CP_ASYNC16(base + off,
                       gX + (size_t)(mbase + row) * IN_DIM + gk);
            CP_ASYNC16(base + A_BYTES + off,
                       gW + (size_t)(nbase + row) * IN_DIM + gk);
        }
    };

    // ---- prologue: fill 5 stages ----
#pragma unroll
    for (int i = 0; i < STAGES - 1; i++) {
        issue_stage(i, i);
        CP_COMMIT();
    }

    // ---- ldmatrix lane addressing ----
    // A: x4 over rows (lane&15), chunk halves by lane>>4
    const int a_row_l = warp_m * 64 + (lane & 15);
    const int a_cgrp  = lane >> 4;          // 0..1
    // B paired x4 (two n8-tiles per instr):
    //   row   = warp_n*64 + np*16 + (lane&7) + ((lane>>4)&1)*8
    //   chunk = ks*2 + ((lane>>3)&1)
    const int b_row_l = warp_n * 64 + (lane & 7) + (((lane >> 4) & 1) << 3);
    const int b_cgrp  = (lane >> 3) & 1;

    float acc[4][8][4] = {};   // [mt][nt][frag] = 128 regs

    int s = 0;
    for (int kt = 0; kt < KT; kt++) {
        CP_WAIT4();          // stage kt's group retired (own view)
        __syncthreads();     // all 4 warps done with stage kt-1's slot

        // prefetch stage kt+5 into the slot read at iteration kt-1
        const int ktn = kt + STAGES - 1;
        if (ktn < KT) {
            int sn = s + STAGES - 1;
            if (sn >= STAGES) sn -= STAGES;
            issue_stage(ktn, sn);
        }
        CP_COMMIT();

        const uint32_t abase = sb + s * STAGE_BYTES;
        const uint32_t bbase = abase + A_BYTES;

#pragma unroll
        for (int ks = 0; ks < 2; ks++) {
            uint32_t af[4][4];
            uint32_t bf[8][2];
#pragma unroll
            for (int mt = 0; mt < 4; mt++) {
                const int row = a_row_l + mt * 16;
                ldmatrix_x4(af[mt][0], af[mt][1], af[mt][2], af[mt][3],
                            abase + sw_off(row, ks * 2 + a_cgrp));
            }
#pragma unroll
            for (int np = 0; np < 4; np++) {   // two n8-tiles per ldmatrix
                const int row = b_row_l + np * 16;
                ldmatrix_x4(bf[2 * np][0], bf[2 * np][1],
                            bf[2 * np + 1][0], bf[2 * np + 1][1],
                            bbase + sw_off(row, ks * 2 + b_cgrp));
            }
#pragma unroll
            for (int mt = 0; mt < 4; mt++)
#pragma unroll
                for (int nt = 0; nt < 8; nt++)
                    mma16816(acc[mt][nt], af[mt], bf[nt]);
        }

        if (++s == STAGES) s = 0;
    }

    // ---- epilogue: registers -> gmem ----
    const int er = lane >> 2;            // 0..7
    const int ec = (lane & 3) * 2;       // 0,2,4,6
#pragma unroll
    for (int mt = 0; mt < 4; mt++) {
#pragma unroll
        for (int nt = 0; nt < 8; nt++) {
            const int r0 = mbase + warp_m * 64 + mt * 16 + er;
            const int c0 = nbase + warp_n * 64 + nt * 8 + ec;
            float2 v0 = make_float2(acc[mt][nt][0], acc[mt][nt][1]);
            float2 v1 = make_float2(acc[mt][nt][2], acc[mt][nt][3]);
            *reinterpret_cast<float2*>(out + (size_t)r0 * OUT_DIM + c0) = v0;
            *reinterpret_cast<float2*>(out + (size_t)(r0 + 8) * OUT_DIM + c0) = v1;
        }
    }
}

// ============================================================================
// Host side
// ============================================================================
extern "C" void kernel_launch(void* const* d_in, const int* in_sizes, int n_in,
                              void* d_out, int out_size) {
    (void)in_sizes; (void)n_in; (void)out_size;
    const float* x  = (const float*)d_in[0];
    const float* w  = (const float*)d_in[1];
    const float* la = (const float*)d_in[2];
    const float* lb = (const float*)d_in[3];
    float* out = (float*)d_out;

    cvt_x_kernel<<<4096, 256>>>(reinterpret_cast<const float4*>(x));
    build_weff_kernel<<<dim3(IN_DIM / 64, OUT_DIM / 64), 256>>>(w, la, lb);

    cudaFuncSetAttribute(lora_gemm_kernel,
                         cudaFuncAttributeMaxDynamicSharedMemorySize, SMEM_TOTAL);
    lora_gemm_kernel<<<NUM_PID_M * NUM_PID_N, 128, SMEM_TOTAL>>>(out);
}

// round 11
// speedup vs baseline: 1.3555x; 1.0129x over previous
#include <cuda_runtime.h>
#include <cuda_fp16.h>
#include <cstdint>

// ============================================================================
// Problem constants
// ============================================================================
#define IN_DIM   4096
#define OUT_DIM  4096
#define MROWS    8192        // BSZ * SEQ
#define TRANK    64
#define LORA_SCALE 2.0f      // alpha/r = 32/16 for every adapter

// GEMM tiling: CTA 128x128, FOUR warps (128 thr), warp tile 64x64.
// 2 CTAs/SM (load-bearing); 6-stage cp.async pipeline.
#define BM 128
#define BN 128
#define BK 32
#define KT (IN_DIM / BK)          // 128 k-tiles
#define STAGES 6
#define A_BYTES (BM * BK * 2)     // 8192
#define B_BYTES (BN * BK * 2)     // 8192
#define STAGE_BYTES (A_BYTES + B_BYTES)   // 16384
#define SMEM_TOTAL (STAGES * STAGE_BYTES) // 98304 (x2 CTAs = 192KB <= 228KB)

// grid rasterization: group 16 m-tiles per n-panel (48MB working set, L2-fit)
#define NUM_PID_M (MROWS / BM)    // 64
#define NUM_PID_N (OUT_DIM / BN)  // 32
#define GRPM 16

// fused prologue grid split
#define WEFF_BLOCKS 4096          // 64x64 tiles of W_eff
#define CVT_BLOCKS  2048

// ============================================================================
// Device scratch (allocation-free rule: __device__ globals)
// ============================================================================
__device__ __half d_Xh[(size_t)MROWS * IN_DIM];    // 64 MiB
__device__ __half d_Wh[(size_t)OUT_DIM * IN_DIM];  // 32 MiB

// ============================================================================
// PTX helpers
// ============================================================================
__device__ __forceinline__ uint32_t smem_u32(const void* p) {
    uint32_t a;
    asm("{ .reg .u64 t; cvta.to.shared.u64 t, %1; cvt.u32.u64 %0, t; }"
        : "=r"(a) : "l"(p));
    return a;
}

#define CP_ASYNC16(dst, src) \
    asm volatile("cp.async.cg.shared.global [%0], [%1], 16;" \
                 :: "r"(dst), "l"(src) : "memory")
#define CP_COMMIT() asm volatile("cp.async.commit_group;" ::: "memory")
#define CP_WAIT4()  asm volatile("cp.async.wait_group 4;" ::: "memory")

__device__ __forceinline__ void ldmatrix_x4(uint32_t& r0, uint32_t& r1,
                                            uint32_t& r2, uint32_t& r3,
                                            uint32_t addr) {
    asm volatile("ldmatrix.sync.aligned.m8n8.x4.shared.b16 {%0,%1,%2,%3}, [%4];"
                 : "=r"(r0), "=r"(r1), "=r"(r2), "=r"(r3) : "r"(addr));
}
__device__ __forceinline__ void mma16816(float* c, const uint32_t* a,
                                         const uint32_t* b) {
    asm volatile(
        "mma.sync.aligned.m16n8k16.row.col.f32.f16.f16.f32 "
        "{%0,%1,%2,%3}, {%4,%5,%6,%7}, {%8,%9}, {%0,%1,%2,%3};"
        : "+f"(c[0]), "+f"(c[1]), "+f"(c[2]), "+f"(c[3])
        : "r"(a[0]), "r"(a[1]), "r"(a[2]), "r"(a[3]), "r"(b[0]), "r"(b[1]));
}

// Swizzle for 64-byte rows, 16B chunks: phys_chunk = chunk ^ ((row>>1)&3)
__device__ __forceinline__ uint32_t sw_off(int row, int chunk) {
    return (uint32_t)(row * 64 + ((chunk ^ ((row >> 1) & 3)) << 4));
}

// ============================================================================
// Fused prologue: blocks [0, WEFF_BLOCKS) build W_eff = W + 2*B@A -> d_Wh fp16;
// blocks [WEFF_BLOCKS, WEFF_BLOCKS+CVT_BLOCKS) convert x fp32 -> d_Xh fp16.
// Running both concurrently overlaps their independent DRAM streams.
// ============================================================================
__global__ void __launch_bounds__(256) fused_prologue_kernel(
    const float4* __restrict__ x,
    const float* __restrict__ W,
    const float* __restrict__ A,   // [64, 4096]
    const float* __restrict__ B) { // [4096, 64]
    __shared__ float sA[64][65];
    __shared__ float sB[64][65];
    const int tid = threadIdx.x;

    if (blockIdx.x < WEFF_BLOCKS) {
        // ---- W_eff tile: 64(n) x 64(k) ----
        const int kb = blockIdx.x & 63;
        const int nb = blockIdx.x >> 6;
        const int n0 = nb * 64;
        const int k0 = kb * 64;

        for (int t = tid; t < 64 * 64; t += 256) {
            int i = t >> 6, c = t & 63;
            sA[i][c] = A[i * IN_DIM + k0 + c];
            sB[i][c] = LORA_SCALE * B[(size_t)(n0 + i) * TRANK + c];
        }
        __syncthreads();

        const int tj = tid & 15, ti = tid >> 4;
        float acc[4][4] = {};
#pragma unroll 8
        for (int r = 0; r < 64; r++) {
            float bv[4], av[4];
#pragma unroll
            for (int q = 0; q < 4; q++) { bv[q] = sB[ti * 4 + q][r]; av[q] = sA[r][tj * 4 + q]; }
#pragma unroll
            for (int p = 0; p < 4; p++)
#pragma unroll
                for (int q = 0; q < 4; q++) acc[p][q] += bv[p] * av[q];
        }
#pragma unroll
        for (int p = 0; p < 4; p++) {
            int n = n0 + ti * 4 + p;
#pragma unroll
            for (int q = 0; q < 4; q++) {
                int k = k0 + tj * 4 + q;
                d_Wh[(size_t)n * IN_DIM + k] =
                    __float2half_rn(W[(size_t)n * IN_DIM + k] + acc[p][q]);
            }
        }
    } else {
        // ---- x fp32 -> fp16 ----
        const int n8 = (MROWS * IN_DIM) / 8;
        const int stride = CVT_BLOCKS * 256;
        for (int i = (blockIdx.x - WEFF_BLOCKS) * 256 + tid; i < n8; i += stride) {
            float4 a = x[2 * i];
            float4 b = x[2 * i + 1];
            __half2 h0 = __floats2half2_rn(a.x, a.y);
            __half2 h1 = __floats2half2_rn(a.z, a.w);
            __half2 h2 = __floats2half2_rn(b.x, b.y);
            __half2 h3 = __floats2half2_rn(b.z, b.w);
            uint4 v;
            v.x = *reinterpret_cast<uint32_t*>(&h0);
            v.y = *reinterpret_cast<uint32_t*>(&h1);
            v.z = *reinterpret_cast<uint32_t*>(&h2);
            v.w = *reinterpret_cast<uint32_t*>(&h3);
            reinterpret_cast<uint4*>(d_Xh)[i] = v;
        }
    }
}

// ============================================================================
// Main GEMM: out[8192,4096] = Xh @ Whᵀ  (fp16 in, fp32 accum, mma.sync)
// CTA 128x128, 4 warps (2m x 2n), warp tile 64x64, 6-stage pipeline,
// per-k-tile wait_group(4) + __syncthreads. 2 CTAs/SM.
// ============================================================================
__global__ void __launch_bounds__(128, 2) lora_gemm_kernel(float* __restrict__ out) {
    extern __shared__ __align__(1024) char smem[];
    const uint32_t sb = smem_u32(smem);
    const int tid = threadIdx.x;
    const int wid = tid >> 5, lane = tid & 31;
    const int warp_m = wid & 1;          // 0..1  (64 rows each)
    const int warp_n = wid >> 1;         // 0..1  (64 cols each)

    // ---- grouped rasterization ----
    const int pid = blockIdx.x;
    const int group_size = GRPM * NUM_PID_N;
    const int group_id = pid / group_size;
    const int pid_in = pid - group_id * group_size;
    const int pid_m = group_id * GRPM + (pid_in % GRPM);
    const int pid_n = pid_in / GRPM;

    const int mbase = pid_m * BM;
    const int nbase = pid_n * BN;

    const __half* gX = d_Xh;
    const __half* gW = d_Wh;

    // ---- cp.async loader: 128 threads, 16B chunks, 4 row-passes each ----
    const int ld_row = tid >> 2;          // 0..31
    const int ld_c   = tid & 3;           // 0..3

    auto issue_stage = [&](int kt, int s) {
        const uint32_t base = sb + s * STAGE_BYTES;
        const size_t gk = (size_t)kt * BK + ld_c * 8;
#pragma unroll
        for (int p = 0; p < 4; p++) {
            const int row = ld_row + p * 32;
            const uint32_t off = sw_off(row, ld_c);
            CP_ASYNC16(base + off,
                       gX + (size_t)(mbase + row) * IN_DIM + gk);
            CP_ASYNC16(base + A_BYTES + off,
                       gW + (size_t)(nbase + row) * IN_DIM + gk);
        }
    };

    // ---- prologue: fill 5 stages ----
#pragma unroll
    for (int i = 0; i < STAGES - 1; i++) {
        issue_stage(i, i);
        CP_COMMIT();
    }

    // ---- ldmatrix lane addressing ----
    const int a_row_l = warp_m * 64 + (lane & 15);
    const int a_cgrp  = lane >> 4;          // 0..1
    const int b_row_l = warp_n * 64 + (lane & 7) + (((lane >> 4) & 1) << 3);
    const int b_cgrp  = (lane >> 3) & 1;

    float acc[4][8][4] = {};   // [mt][nt][frag] = 128 regs

    int s = 0;
    for (int kt = 0; kt < KT; kt++) {
        CP_WAIT4();          // stage kt's group retired (own view)
        __syncthreads();     // all 4 warps done with stage kt-1's slot

        // prefetch stage kt+5 into the slot read at iteration kt-1
        const int ktn = kt + STAGES - 1;
        if (ktn < KT) {
            int sn = s + STAGES - 1;
            if (sn >= STAGES) sn -= STAGES;
            issue_stage(ktn, sn);
        }
        CP_COMMIT();

        const uint32_t abase = sb + s * STAGE_BYTES;
        const uint32_t bbase = abase + A_BYTES;

#pragma unroll
        for (int ks = 0; ks < 2; ks++) {
            uint32_t af[4][4];
            uint32_t bf[8][2];
#pragma unroll
            for (int mt = 0; mt < 4; mt++) {
                const int row = a_row_l + mt * 16;
                ldmatrix_x4(af[mt][0], af[mt][1], af[mt][2], af[mt][3],
                            abase + sw_off(row, ks * 2 + a_cgrp));
            }
#pragma unroll
            for (int np = 0; np < 4; np++) {   // two n8-tiles per ldmatrix
                const int row = b_row_l + np * 16;
                ldmatrix_x4(bf[2 * np][0], bf[2 * np][1],
                            bf[2 * np + 1][0], bf[2 * np + 1][1],
                            bbase + sw_off(row, ks * 2 + b_cgrp));
            }
#pragma unroll
            for (int mt = 0; mt < 4; mt++)
#pragma unroll
                for (int nt = 0; nt < 8; nt++)
                    mma16816(acc[mt][nt], af[mt], bf[nt]);
        }

        if (++s == STAGES) s = 0;
    }

    // ---- epilogue: registers -> gmem ----
    const int er = lane >> 2;            // 0..7
    const int ec = (lane & 3) * 2;       // 0,2,4,6
#pragma unroll
    for (int mt = 0; mt < 4; mt++) {
#pragma unroll
        for (int nt = 0; nt < 8; nt++) {
            const int r0 = mbase + warp_m * 64 + mt * 16 + er;
            const int c0 = nbase + warp_n * 64 + nt * 8 + ec;
            float2 v0 = make_float2(acc[mt][nt][0], acc[mt][nt][1]);
            float2 v1 = make_float2(acc[mt][nt][2], acc[mt][nt][3]);
            *reinterpret_cast<float2*>(out + (size_t)r0 * OUT_DIM + c0) = v0;
            *reinterpret_cast<float2*>(out + (size_t)(r0 + 8) * OUT_DIM + c0) = v1;
        }
    }
}

// ============================================================================
// Host side
// ============================================================================
extern "C" void kernel_launch(void* const* d_in, const int* in_sizes, int n_in,
                              void* d_out, int out_size) {
    (void)in_sizes; (void)n_in; (void)out_size;
    const float* x  = (const float*)d_in[0];
    const float* w  = (const float*)d_in[1];
    const float* la = (const float*)d_in[2];
    const float* lb = (const float*)d_in[3];
    float* out = (float*)d_out;

    fused_prologue_kernel<<<WEFF_BLOCKS + CVT_BLOCKS, 256>>>(
        reinterpret_cast<const float4*>(x), w, la, lb);

    cudaFuncSetAttribute(lora_gemm_kernel,
                         cudaFuncAttributeMaxDynamicSharedMemorySize, SMEM_TOTAL);
    lora_gemm_kernel<<<NUM_PID_M * NUM_PID_N, 128, SMEM_TOTAL>>>(out);
}

// round 12
// speedup vs baseline: 1.4331x; 1.0572x over previous
#include <cuda_runtime.h>
#include <cuda_fp16.h>
#include <cstdint>

// ============================================================================
// Problem constants
// ============================================================================
#define IN_DIM   4096
#define OUT_DIM  4096
#define MROWS    8192        // BSZ * SEQ
#define TRANK    64
#define LORA_SCALE 2.0f      // alpha/r = 32/16 for every adapter

// GEMM tiling: CTA 128x128, FOUR warps (128 thr), warp tile 64x64.
// 2 CTAs/SM (load-bearing); 6-stage cp.async pipeline.  [proven: 553us]
#define BM 128
#define BN 128
#define BK 32
#define KT (IN_DIM / BK)          // 128 k-tiles
#define STAGES 6
#define A_BYTES (BM * BK * 2)     // 8192
#define B_BYTES (BN * BK * 2)     // 8192
#define STAGE_BYTES (A_BYTES + B_BYTES)   // 16384
#define SMEM_TOTAL (STAGES * STAGE_BYTES) // 98304 (x2 CTAs = 192KB <= 228KB)

// grid rasterization
#define NUM_PID_M (MROWS / BM)    // 64
#define NUM_PID_N (OUT_DIM / BN)  // 32
#define GRPM 16

// fused prologue (128-thread blocks)
// W_eff tiles: 128(n) x 64(k) per block -> (4096/128)*(4096/64) = 2048 blocks
#define WEFF_BLOCKS 2048
#define CVT_BLOCKS  4096

// padded smem rows for the weff mma: 64 fp16 = 128B data + 16B pad = 144B
#define WROW 144

// ============================================================================
// Device scratch (allocation-free rule: __device__ globals)
// ============================================================================
__device__ __half d_Xh[(size_t)MROWS * IN_DIM];    // 64 MiB
__device__ __half d_Wh[(size_t)OUT_DIM * IN_DIM];  // 32 MiB

// ============================================================================
// PTX helpers
// ============================================================================
__device__ __forceinline__ uint32_t smem_u32(const void* p) {
    uint32_t a;
    asm("{ .reg .u64 t; cvta.to.shared.u64 t, %1; cvt.u32.u64 %0, t; }"
        : "=r"(a) : "l"(p));
    return a;
}

#define CP_ASYNC16(dst, src) \
    asm volatile("cp.async.cg.shared.global [%0], [%1], 16;" \
                 :: "r"(dst), "l"(src) : "memory")
#define CP_COMMIT() asm volatile("cp.async.commit_group;" ::: "memory")
#define CP_WAIT4()  asm volatile("cp.async.wait_group 4;" ::: "memory")

__device__ __forceinline__ void ldmatrix_x4(uint32_t& r0, uint32_t& r1,
                                            uint32_t& r2, uint32_t& r3,
                                            uint32_t addr) {
    asm volatile("ldmatrix.sync.aligned.m8n8.x4.shared.b16 {%0,%1,%2,%3}, [%4];"
                 : "=r"(r0), "=r"(r1), "=r"(r2), "=r"(r3) : "r"(addr));
}
__device__ __forceinline__ void ldmatrix_x4_trans(uint32_t& r0, uint32_t& r1,
                                                  uint32_t& r2, uint32_t& r3,
                                                  uint32_t addr) {
    asm volatile("ldmatrix.sync.aligned.m8n8.x4.trans.shared.b16 {%0,%1,%2,%3}, [%4];"
                 : "=r"(r0), "=r"(r1), "=r"(r2), "=r"(r3) : "r"(addr));
}
__device__ __forceinline__ void mma16816(float* c, const uint32_t* a,
                                         const uint32_t* b) {
    asm volatile(
        "mma.sync.aligned.m16n8k16.row.col.f32.f16.f16.f32 "
        "{%0,%1,%2,%3}, {%4,%5,%6,%7}, {%8,%9}, {%0,%1,%2,%3};"
        : "+f"(c[0]), "+f"(c[1]), "+f"(c[2]), "+f"(c[3])
        : "r"(a[0]), "r"(a[1]), "r"(a[2]), "r"(a[3]), "r"(b[0]), "r"(b[1]));
}

// Swizzle for 64-byte rows, 16B chunks: phys_chunk = chunk ^ ((row>>1)&3)
__device__ __forceinline__ uint32_t sw_off(int row, int chunk) {
    return (uint32_t)(row * 64 + ((chunk ^ ((row >> 1) & 3)) << 4));
}

// ============================================================================
// Fused prologue (128 threads/block):
//   blocks [0, WEFF_BLOCKS):  W_eff = W + 2*B@A -> d_Wh fp16 via mma.sync
//   blocks [WEFF_BLOCKS, +CVT_BLOCKS): x fp32 -> d_Xh fp16
// ============================================================================
__global__ void __launch_bounds__(128) fused_prologue_kernel(
    const float4* __restrict__ x,
    const float* __restrict__ W,
    const float* __restrict__ A,    // [64, 4096] fp32
    const float* __restrict__ Bl) { // [4096, 64] fp32
    __shared__ __align__(16) char psm[128 * WROW + 64 * WROW];  // 27648 B
    const int tid = threadIdx.x;

    if (blockIdx.x < WEFF_BLOCKS) {
        // ---- tensor-core W_eff tile: 128 n-rows x 64 k-cols, rank K=64 ----
        const int nb = blockIdx.x >> 6;       // 0..31
        const int kb = blockIdx.x & 63;       // 0..63
        const int n0 = nb * 128;
        const int k0 = kb * 64;

        __half* sB = reinterpret_cast<__half*>(psm);               // [128][64] pad WROW: B[n][r]*2
        __half* sA = reinterpret_cast<__half*>(psm + 128 * WROW);  // [64][64]  pad WROW: A[r][k]
        const uint32_t sb_u = smem_u32(sB);
        const uint32_t sa_u = smem_u32(sA);

        // load B rows (one row per thread): 64 fp32 -> fp16 *2
        {
            const float4* src = reinterpret_cast<const float4*>(
                Bl + (size_t)(n0 + tid) * TRANK);
            char* dst = psm + tid * WROW;
#pragma unroll
            for (int c = 0; c < 16; c++) {
                float4 v = src[c];
                __half2 h0 = __floats2half2_rn(LORA_SCALE * v.x, LORA_SCALE * v.y);
                __half2 h1 = __floats2half2_rn(LORA_SCALE * v.z, LORA_SCALE * v.w);
                uint2 u;
                u.x = *reinterpret_cast<uint32_t*>(&h0);
                u.y = *reinterpret_cast<uint32_t*>(&h1);
                *reinterpret_cast<uint2*>(dst + c * 8) = u;
            }
        }
        // load A rows: 64 rows x 64 cols, 2 threads per row (32 cols each)
        {
            const int r = tid & 63;
            const int hsel = tid >> 6;          // 0..1
            const float4* src = reinterpret_cast<const float4*>(
                A + (size_t)r * IN_DIM + k0 + hsel * 32);
            char* dst = psm + 128 * WROW + r * WROW + hsel * 64;
#pragma unroll
            for (int c = 0; c < 8; c++) {
                float4 v = src[c];
                __half2 h0 = __floats2half2_rn(v.x, v.y);
                __half2 h1 = __floats2half2_rn(v.z, v.w);
                uint2 u;
                u.x = *reinterpret_cast<uint32_t*>(&h0);
                u.y = *reinterpret_cast<uint32_t*>(&h1);
                *reinterpret_cast<uint2*>(dst + c * 8) = u;
            }
        }
        __syncthreads();

        const int wid = tid >> 5, lane = tid & 31;
        // A-operand (= B lora) addressing: row-major [M=128][K=64]
        const int ar = wid * 32 + (lane & 15);
        const int acg = lane >> 4;              // 16B chunk within k16 block
        // B-operand (= A lora, [K][N] row-major) via ldmatrix.x4.trans:
        //   lane group g=lane>>3: k-half (g&1), nt offset (g>>1)
        const int br = ((lane >> 3) & 1) * 8 + (lane & 7);   // k-row within 16
        const int bnoff = lane >> 4;            // 0..1 -> nt, nt+1

        float acc[2][8][4] = {};
#pragma unroll
        for (int kt = 0; kt < 4; kt++) {
            uint32_t af[2][4];
            uint32_t bf[8][2];
#pragma unroll
            for (int mt = 0; mt < 2; mt++) {
                const uint32_t addr = sb_u + (uint32_t)(ar + mt * 16) * WROW
                                    + kt * 32 + acg * 16;
                ldmatrix_x4(af[mt][0], af[mt][1], af[mt][2], af[mt][3], addr);
            }
#pragma unroll
            for (int nt = 0; nt < 8; nt += 2) {
                const uint32_t addr = sa_u + (uint32_t)(kt * 16 + br) * WROW
                                    + (nt + bnoff) * 16;
                ldmatrix_x4_trans(bf[nt][0], bf[nt][1],
                                  bf[nt + 1][0], bf[nt + 1][1], addr);
            }
#pragma unroll
            for (int mt = 0; mt < 2; mt++)
#pragma unroll
                for (int nt = 0; nt < 8; nt++)
                    mma16816(acc[mt][nt], af[mt], bf[nt]);
        }

        // epilogue: W (fp32) + acc -> fp16 d_Wh
        const int er = lane >> 2;
        const int ec = (lane & 3) * 2;
#pragma unroll
        for (int mt = 0; mt < 2; mt++) {
#pragma unroll
            for (int nt = 0; nt < 8; nt++) {
                const int r0 = n0 + wid * 32 + mt * 16 + er;
                const int c0 = k0 + nt * 8 + ec;
                float2 w0 = *reinterpret_cast<const float2*>(W + (size_t)r0 * IN_DIM + c0);
                float2 w1 = *reinterpret_cast<const float2*>(W + (size_t)(r0 + 8) * IN_DIM + c0);
                __half2 h0 = __floats2half2_rn(w0.x + acc[mt][nt][0],
                                               w0.y + acc[mt][nt][1]);
                __half2 h1 = __floats2half2_rn(w1.x + acc[mt][nt][2],
                                               w1.y + acc[mt][nt][3]);
                *reinterpret_cast<uint32_t*>(d_Wh + (size_t)r0 * IN_DIM + c0) =
                    *reinterpret_cast<uint32_t*>(&h0);
                *reinterpret_cast<uint32_t*>(d_Wh + (size_t)(r0 + 8) * IN_DIM + c0) =
                    *reinterpret_cast<uint32_t*>(&h1);
            }
        }
    } else {
        // ---- x fp32 -> fp16 ----
        const int n8 = (MROWS * IN_DIM) / 8;
        const int stride = CVT_BLOCKS * 128;
        for (int i = (blockIdx.x - WEFF_BLOCKS) * 128 + tid; i < n8; i += stride) {
            float4 a = x[2 * i];
            float4 b = x[2 * i + 1];
            __half2 h0 = __floats2half2_rn(a.x, a.y);
            __half2 h1 = __floats2half2_rn(a.z, a.w);
            __half2 h2 = __floats2half2_rn(b.x, b.y);
            __half2 h3 = __floats2half2_rn(b.z, b.w);
            uint4 v;
            v.x = *reinterpret_cast<uint32_t*>(&h0);
            v.y = *reinterpret_cast<uint32_t*>(&h1);
            v.z = *reinterpret_cast<uint32_t*>(&h2);
            v.w = *reinterpret_cast<uint32_t*>(&h3);
            reinterpret_cast<uint4*>(d_Xh)[i] = v;
        }
    }
}

// ============================================================================
// Main GEMM: out[8192,4096] = Xh @ Whᵀ  (fp16 in, fp32 accum, mma.sync)
// CTA 128x128, 4 warps (2m x 2n), warp tile 64x64, 6-stage pipeline,
// per-k-tile wait_group(4) + __syncthreads. 2 CTAs/SM.   [UNCHANGED]
// ============================================================================
__global__ void __launch_bounds__(128, 2) lora_gemm_kernel(float* __restrict__ out) {
    extern __shared__ __align__(1024) char smem[];
    const uint32_t sb = smem_u32(smem);
    const int tid = threadIdx.x;
    const int wid = tid >> 5, lane = tid & 31;
    const int warp_m = wid & 1;
    const int warp_n = wid >> 1;

    const int pid = blockIdx.x;
    const int group_size = GRPM * NUM_PID_N;
    const int group_id = pid / group_size;
    const int pid_in = pid - group_id * group_size;
    const int pid_m = group_id * GRPM + (pid_in % GRPM);
    const int pid_n = pid_in / GRPM;

    const int mbase = pid_m * BM;
    const int nbase = pid_n * BN;

    const __half* gX = d_Xh;
    const __half* gW = d_Wh;

    const int ld_row = tid >> 2;
    const int ld_c   = tid & 3;

    auto issue_stage = [&](int kt, int s) {
        const uint32_t base = sb + s * STAGE_BYTES;
        const size_t gk = (size_t)kt * BK + ld_c * 8;
#pragma unroll
        for (int p = 0; p < 4; p++) {
            const int row = ld_row + p * 32;
            const uint32_t off = sw_off(row, ld_c);
            CP_ASYNC16(base + off,
                       gX + (size_t)(mbase + row) * IN_DIM + gk);
            CP_ASYNC16(base + A_BYTES + off,
                       gW + (size_t)(nbase + row) * IN_DIM + gk);
        }
    };

#pragma unroll
    for (int i = 0; i < STAGES - 1; i++) {
        issue_stage(i, i);
        CP_COMMIT();
    }

    const int a_row_l = warp_m * 64 + (lane & 15);
    const int a_cgrp  = lane >> 4;
    const int b_row_l = warp_n * 64 + (lane & 7) + (((lane >> 4) & 1) << 3);
    const int b_cgrp  = (lane >> 3) & 1;

    float acc[4][8][4] = {};

    int s = 0;
    for (int kt = 0; kt < KT; kt++) {
        CP_WAIT4();
        __syncthreads();

        const int ktn = kt + STAGES - 1;
        if (ktn < KT) {
            int sn = s + STAGES - 1;
            if (sn >= STAGES) sn -= STAGES;
            issue_stage(ktn, sn);
        }
        CP_COMMIT();

        const uint32_t abase = sb + s * STAGE_BYTES;
        const uint32_t bbase = abase + A_BYTES;

#pragma unroll
        for (int ks = 0; ks < 2; ks++) {
            uint32_t af[4][4];
            uint32_t bf[8][2];
#pragma unroll
            for (int mt = 0; mt < 4; mt++) {
                const int row = a_row_l + mt * 16;
                ldmatrix_x4(af[mt][0], af[mt][1], af[mt][2], af[mt][3],
                            abase + sw_off(row, ks * 2 + a_cgrp));
            }
#pragma unroll
            for (int np = 0; np < 4; np++) {
                const int row = b_row_l + np * 16;
                ldmatrix_x4(bf[2 * np][0], bf[2 * np][1],
                            bf[2 * np + 1][0], bf[2 * np + 1][1],
                            bbase + sw_off(row, ks * 2 + b_cgrp));
            }
#pragma unroll
            for (int mt = 0; mt < 4; mt++)
#pragma unroll
                for (int nt = 0; nt < 8; nt++)
                    mma16816(acc[mt][nt], af[mt], bf[nt]);
        }

        if (++s == STAGES) s = 0;
    }

    const int er = lane >> 2;
    const int ec = (lane & 3) * 2;
#pragma unroll
    for (int mt = 0; mt < 4; mt++) {
#pragma unroll
        for (int nt = 0; nt < 8; nt++) {
            const int r0 = mbase + warp_m * 64 + mt * 16 + er;
            const int c0 = nbase + warp_n * 64 + nt * 8 + ec;
            float2 v0 = make_float2(acc[mt][nt][0], acc[mt][nt][1]);
            float2 v1 = make_float2(acc[mt][nt][2], acc[mt][nt][3]);
            *reinterpret_cast<float2*>(out + (size_t)r0 * OUT_DIM + c0) = v0;
            *reinterpret_cast<float2*>(out + (size_t)(r0 + 8) * OUT_DIM + c0) = v1;
        }
    }
}

// ============================================================================
// Host side
// ============================================================================
extern "C" void kernel_launch(void* const* d_in, const int* in_sizes, int n_in,
                              void* d_out, int out_size) {
    (void)in_sizes; (void)n_in; (void)out_size;
    const float* x  = (const float*)d_in[0];
    const float* w  = (const float*)d_in[1];
    const float* la = (const float*)d_in[2];
    const float* lb = (const float*)d_in[3];
    float* out = (float*)d_out;

    fused_prologue_kernel<<<WEFF_BLOCKS + CVT_BLOCKS, 128>>>(
        reinterpret_cast<const float4*>(x), w, la, lb);

    cudaFuncSetAttribute(lora_gemm_kernel,
                         cudaFuncAttributeMaxDynamicSharedMemorySize, SMEM_TOTAL);
    lora_gemm_kernel<<<NUM_PID_M * NUM_PID_N, 128, SMEM_TOTAL>>>(out);
}